// round 1
// baseline (speedup 1.0000x reference)
#include <cuda_runtime.h>
#include <cstdint>

// Problem constants
#define Bq 4
#define LQ 3000
#define LKk 750
#define Cc 64
#define NHh 4
#define DKk 16
#define Ff 256
#define RQ (Bq*LQ)      // 12000
#define RK (Bq*LKk)     // 3000

// ---------------- scratch (static device globals; no cudaMalloc allowed) ---
static __device__ float g_qp [RQ*Cc];
static __device__ float g_kp [RK*Cc];
static __device__ float g_vp [RK*Cc];
static __device__ float g_att[RQ*Cc];
static __device__ float g_o1 [RQ*Cc];
static __device__ float g_x  [RQ*Cc];
static __device__ float g_h1 [RQ*Ff];
static __device__ float g_x2 [RQ*Cc];
static __device__ float g_qn [RQ*Cc];
static __device__ float g_t1 [RQ*Cc];
static __device__ float g_sg [RQ*Cc];
static __device__ float g_awg[RQ*Cc];
static __device__ float g_xn [RQ*Cc];

// ---------------- GEMM: Y[rows,N] = act(X[rows,K] @ W[K,N] + bias) (*mul) ---
// act: 0=none, 1=relu, 2=sigmoid
template<int K, int N>
__global__ __launch_bounds__(256)
void gemm_kernel(const float* __restrict__ X, const float* __restrict__ W,
                 const float* __restrict__ bias, const float* __restrict__ mulsrc,
                 float* __restrict__ Y, int rows, int act)
{
    extern __shared__ float4 Ws4[];              // K*N/4 float4
    constexpr int C4 = N / 4;
    for (int i = threadIdx.x; i < K * C4; i += 256)
        Ws4[i] = reinterpret_cast<const float4*>(W)[i];
    __syncthreads();

    const int c4 = threadIdx.x % C4;
    const int rbase = blockIdx.x * 64;
    for (int rr = threadIdx.x / C4; rr < 64; rr += 256 / C4) {
        int row = rbase + rr;
        if (row >= rows) break;
        float ax = 0.f, ay = 0.f, az = 0.f, aw = 0.f;
        const float4* xrow = reinterpret_cast<const float4*>(X + (size_t)row * K);
#pragma unroll 8
        for (int k4 = 0; k4 < K / 4; k4++) {
            float4 xq = __ldg(&xrow[k4]);
            float4 w0 = Ws4[(k4*4+0)*C4 + c4];
            float4 w1 = Ws4[(k4*4+1)*C4 + c4];
            float4 w2 = Ws4[(k4*4+2)*C4 + c4];
            float4 w3 = Ws4[(k4*4+3)*C4 + c4];
            ax += xq.x*w0.x + xq.y*w1.x + xq.z*w2.x + xq.w*w3.x;
            ay += xq.x*w0.y + xq.y*w1.y + xq.z*w2.y + xq.w*w3.y;
            az += xq.x*w0.z + xq.y*w1.z + xq.z*w2.z + xq.w*w3.z;
            aw += xq.x*w0.w + xq.y*w1.w + xq.z*w2.w + xq.w*w3.w;
        }
        if (bias) {
            float4 bv = __ldg(&reinterpret_cast<const float4*>(bias)[c4]);
            ax += bv.x; ay += bv.y; az += bv.z; aw += bv.w;
        }
        if (act == 1) {
            ax = fmaxf(ax, 0.f); ay = fmaxf(ay, 0.f);
            az = fmaxf(az, 0.f); aw = fmaxf(aw, 0.f);
        } else if (act == 2) {
            ax = 1.f/(1.f+__expf(-ax)); ay = 1.f/(1.f+__expf(-ay));
            az = 1.f/(1.f+__expf(-az)); aw = 1.f/(1.f+__expf(-aw));
        }
        if (mulsrc) {
            float4 mv = __ldg(&reinterpret_cast<const float4*>(mulsrc + (size_t)row*N)[c4]);
            ax *= mv.x; ay *= mv.y; az *= mv.z; aw *= mv.w;
        }
        float4 o; o.x = ax; o.y = ay; o.z = az; o.w = aw;
        reinterpret_cast<float4*>(Y + (size_t)row * N)[c4] = o;
    }
}

// ---------------- attention (per (b,h), thread-per-query, two-pass) --------
// TOPK=false: plain softmax.  TOPK=true: keep weights >= 16th-largest, renorm.
template<bool TOPK>
__global__ __launch_bounds__(256, 2)
void attn_kernel(const float* __restrict__ qp, const float* __restrict__ kp,
                 const float* __restrict__ vp, float* __restrict__ outp)
{
    extern __shared__ float4 sKV[];  // [0,3000): K head slice, [3000,6000): V
    const int b = blockIdx.y >> 2, h = blockIdx.y & 3;
    const float* kbase = kp + ((size_t)b * LKk) * Cc + h * DKk;
    const float* vbase = vp + ((size_t)b * LKk) * Cc + h * DKk;
    for (int idx = threadIdx.x; idx < LKk * 4; idx += 256) {
        int j = idx >> 2, dd = idx & 3;
        sKV[idx]            = *reinterpret_cast<const float4*>(kbase + j*Cc + dd*4);
        sKV[idx + LKk*4]    = *reinterpret_cast<const float4*>(vbase + j*Cc + dd*4);
    }
    __syncthreads();

    int qi = blockIdx.x * 256 + threadIdx.x;
    if (qi >= LQ) return;
    const float* qrow = qp + ((size_t)(b * LQ + qi)) * Cc + h * DKk;
    float4 q0 = *reinterpret_cast<const float4*>(qrow + 0);
    float4 q1 = *reinterpret_cast<const float4*>(qrow + 4);
    float4 q2 = *reinterpret_cast<const float4*>(qrow + 8);
    float4 q3 = *reinterpret_cast<const float4*>(qrow + 12);
    const float sc = 0.25f;  // 1/sqrt(dk=16)
    q0.x*=sc;q0.y*=sc;q0.z*=sc;q0.w*=sc; q1.x*=sc;q1.y*=sc;q1.z*=sc;q1.w*=sc;
    q2.x*=sc;q2.y*=sc;q2.z*=sc;q2.w*=sc; q3.x*=sc;q3.y*=sc;q3.z*=sc;q3.w*=sc;

    float t[16];
    if (TOPK) {
#pragma unroll
        for (int k = 0; k < 16; k++) t[k] = -3.4e38f;  // ascending; t[0]=threshold
    }
    float m = -3.4e38f;

    // pass 1: max logit (+ top-16 threshold for AWG)
    for (int j = 0; j < LKk; j++) {
        const float4* kj = &sKV[j * 4];
        float4 k0 = kj[0], k1 = kj[1], k2 = kj[2], k3 = kj[3];
        float s = q0.x*k0.x + q0.y*k0.y + q0.z*k0.z + q0.w*k0.w
                + q1.x*k1.x + q1.y*k1.y + q1.z*k1.z + q1.w*k1.w
                + q2.x*k2.x + q2.y*k2.y + q2.z*k2.z + q2.w*k2.w
                + q3.x*k3.x + q3.y*k3.y + q3.z*k3.z + q3.w*k3.w;
        m = fmaxf(m, s);
        if (TOPK) {
            if (s > t[0]) {   // branch-free sorted insert, static indices only
#pragma unroll
                for (int k = 0; k < 15; k++)
                    t[k] = (t[k+1] < s) ? t[k+1] : ((t[k] < s) ? s : t[k]);
                if (t[15] < s) t[15] = s;
            }
        }
    }
    const float thr = TOPK ? t[0] : -3.4e38f;

    // pass 2: gated exp-sum and weighted V accumulation
    float l = 0.f;
    float4 o0 = {0,0,0,0}, o1v = {0,0,0,0}, o2 = {0,0,0,0}, o3 = {0,0,0,0};
    for (int j = 0; j < LKk; j++) {
        const float4* kj = &sKV[j * 4];
        float4 k0 = kj[0], k1 = kj[1], k2 = kj[2], k3 = kj[3];
        float s = q0.x*k0.x + q0.y*k0.y + q0.z*k0.z + q0.w*k0.w
                + q1.x*k1.x + q1.y*k1.y + q1.z*k1.z + q1.w*k1.w
                + q2.x*k2.x + q2.y*k2.y + q2.z*k2.z + q2.w*k2.w
                + q3.x*k3.x + q3.y*k3.y + q3.z*k3.z + q3.w*k3.w;
        if (!TOPK || s >= thr) {
            float p = __expf(s - m);
            l += p;
            const float4* vj = &sKV[LKk*4 + j*4];
            float4 v0 = vj[0], v1 = vj[1], v2 = vj[2], v3 = vj[3];
            o0.x += p*v0.x; o0.y += p*v0.y; o0.z += p*v0.z; o0.w += p*v0.w;
            o1v.x += p*v1.x; o1v.y += p*v1.y; o1v.z += p*v1.z; o1v.w += p*v1.w;
            o2.x += p*v2.x; o2.y += p*v2.y; o2.z += p*v2.z; o2.w += p*v2.w;
            o3.x += p*v3.x; o3.y += p*v3.y; o3.z += p*v3.z; o3.w += p*v3.w;
        }
    }
    float inv = 1.f / l;
    float* orow = outp + ((size_t)(b * LQ + qi)) * Cc + h * DKk;
    float4 w0 = {o0.x*inv, o0.y*inv, o0.z*inv, o0.w*inv};
    float4 w1 = {o1v.x*inv, o1v.y*inv, o1v.z*inv, o1v.w*inv};
    float4 w2 = {o2.x*inv, o2.y*inv, o2.z*inv, o2.w*inv};
    float4 w3 = {o3.x*inv, o3.y*inv, o3.z*inv, o3.w*inv};
    *reinterpret_cast<float4*>(orow + 0)  = w0;
    *reinterpret_cast<float4*>(orow + 4)  = w1;
    *reinterpret_cast<float4*>(orow + 8)  = w2;
    *reinterpret_cast<float4*>(orow + 12) = w3;
}

// ---------------- LayerNorm: y = LN(a (+res)) * g + be ; warp per row ------
__global__ __launch_bounds__(256)
void ln_kernel(const float* __restrict__ a, const float* __restrict__ res,
               const float* __restrict__ g, const float* __restrict__ be,
               float* __restrict__ y, int rows)
{
    int w = (blockIdx.x * 256 + threadIdx.x) >> 5;
    int lane = threadIdx.x & 31;
    if (w >= rows) return;
    const float* ar = a + (size_t)w * Cc;
    float v0 = ar[lane], v1 = ar[lane + 32];
    if (res) { v0 += res[(size_t)w*Cc + lane]; v1 += res[(size_t)w*Cc + lane + 32]; }
    float s = v0 + v1, ss = v0*v0 + v1*v1;
#pragma unroll
    for (int o = 16; o; o >>= 1) {
        s  += __shfl_xor_sync(0xffffffffu, s, o);
        ss += __shfl_xor_sync(0xffffffffu, ss, o);
    }
    float mean = s * (1.f/64.f);
    float var = ss * (1.f/64.f) - mean * mean;
    float rstd = rsqrtf(var + 1e-6f);
    y[(size_t)w*Cc + lane]      = (v0 - mean) * rstd * g[lane]      + be[lane];
    y[(size_t)w*Cc + lane + 32] = (v1 - mean) * rstd * g[lane + 32] + be[lane + 32];
}

// ---------------- GLU combine: x = qn + sg * sigmoid(awg) ------------------
__global__ __launch_bounds__(256)
void glu_kernel(const float* __restrict__ qn, const float* __restrict__ sg,
                const float* __restrict__ awg, float* __restrict__ y, int n)
{
    int i = blockIdx.x * 256 + threadIdx.x;
    if (i >= n) return;
    y[i] = qn[i] + sg[i] * (1.f / (1.f + __expf(-awg[i])));
}

// ---------------- head: out = sigmoid(x @ fcW + fcb) -----------------------
__global__ __launch_bounds__(256)
void head_kernel(const float* __restrict__ x, const float* __restrict__ fw,
                 const float* __restrict__ fb, float* __restrict__ out, int rows)
{
    __shared__ float w[Cc];
    __shared__ float b0;
    if (threadIdx.x < Cc) w[threadIdx.x] = fw[threadIdx.x];
    if (threadIdx.x == 0) b0 = fb[0];
    __syncthreads();
    int r = blockIdx.x * 256 + threadIdx.x;
    if (r >= rows) return;
    const float4* xr = reinterpret_cast<const float4*>(x + (size_t)r * Cc);
    float acc = b0;
#pragma unroll
    for (int k4 = 0; k4 < 16; k4++) {
        float4 xv = __ldg(&xr[k4]);
        acc += xv.x * w[k4*4+0] + xv.y * w[k4*4+1] + xv.z * w[k4*4+2] + xv.w * w[k4*4+3];
    }
    out[r] = 1.f / (1.f + __expf(-acc));
}

// ---------------- host orchestration ---------------------------------------
extern "C" void kernel_launch(void* const* d_in, const int* in_sizes, int n_in,
                              void* d_out, int out_size)
{
    const float* q        = (const float*)d_in[0];
    const float* enc      = (const float*)d_in[1];
    const float* cal_Wq   = (const float*)d_in[2];
    const float* cal_Wk   = (const float*)d_in[3];
    const float* cal_Wv   = (const float*)d_in[4];
    const float* cal_Wo   = (const float*)d_in[5];
    const float* cal_ln1g = (const float*)d_in[6];
    const float* cal_ln1b = (const float*)d_in[7];
    const float* cal_W1   = (const float*)d_in[8];
    const float* cal_b1   = (const float*)d_in[9];
    const float* cal_W2   = (const float*)d_in[10];
    const float* cal_b2   = (const float*)d_in[11];
    const float* cal_ln2g = (const float*)d_in[12];
    const float* cal_ln2b = (const float*)d_in[13];
    const float* m_ln_g   = (const float*)d_in[14];
    const float* m_ln_b   = (const float*)d_in[15];
    const float* m_fc1_W  = (const float*)d_in[16];
    const float* m_fc1_b  = (const float*)d_in[17];
    const float* m_fc2_W  = (const float*)d_in[18];
    const float* m_fc2_b  = (const float*)d_in[19];
    const float* m_Wq     = (const float*)d_in[20];
    const float* m_Wk     = (const float*)d_in[21];
    const float* m_Wv     = (const float*)d_in[22];
    const float* m_Wo     = (const float*)d_in[23];
    const float* m_aln_g  = (const float*)d_in[24];
    const float* m_aln_b  = (const float*)d_in[25];
    const float* fc_W     = (const float*)d_in[26];
    const float* fc_b     = (const float*)d_in[27];

    float *qp, *kp, *vp, *att, *o1, *x, *h1, *x2, *qn, *t1, *sg, *awg, *xn;
    cudaGetSymbolAddress((void**)&qp,  g_qp);
    cudaGetSymbolAddress((void**)&kp,  g_kp);
    cudaGetSymbolAddress((void**)&vp,  g_vp);
    cudaGetSymbolAddress((void**)&att, g_att);
    cudaGetSymbolAddress((void**)&o1,  g_o1);
    cudaGetSymbolAddress((void**)&x,   g_x);
    cudaGetSymbolAddress((void**)&h1,  g_h1);
    cudaGetSymbolAddress((void**)&x2,  g_x2);
    cudaGetSymbolAddress((void**)&qn,  g_qn);
    cudaGetSymbolAddress((void**)&t1,  g_t1);
    cudaGetSymbolAddress((void**)&sg,  g_sg);
    cudaGetSymbolAddress((void**)&awg, g_awg);
    cudaGetSymbolAddress((void**)&xn,  g_xn);

    cudaFuncSetAttribute(attn_kernel<false>, cudaFuncAttributeMaxDynamicSharedMemorySize, 96000);
    cudaFuncSetAttribute(attn_kernel<true>,  cudaFuncAttributeMaxDynamicSharedMemorySize, 96000);
    cudaFuncSetAttribute((gemm_kernel<64,256>), cudaFuncAttributeMaxDynamicSharedMemorySize, 65536);
    cudaFuncSetAttribute((gemm_kernel<256,64>), cudaFuncAttributeMaxDynamicSharedMemorySize, 65536);

    const int smem64 = 64 * 64 * 4;     // 16 KB
    const int gQ = (RQ + 63) / 64;      // 188
    const int gK = (RK + 63) / 64;      // 47
    const int lnG = (RQ * 32 + 255) / 256;  // 1500
    dim3 agrid((LQ + 255) / 256, Bq * NHh); // (12, 16)

    auto GEMM64 = [&](const float* X, const float* W, const float* bias,
                      const float* mul, float* Y, int rows, int act) {
        gemm_kernel<64,64><<<(rows + 63) / 64, 256, smem64>>>(X, W, bias, mul, Y, rows, act);
    };

    // ---- cross_attn_layer ----
    GEMM64(q,   cal_Wq, nullptr, nullptr, qp, RQ, 0);
    GEMM64(enc, cal_Wk, nullptr, nullptr, kp, RK, 0);
    GEMM64(enc, cal_Wv, nullptr, nullptr, vp, RK, 0);
    attn_kernel<false><<<agrid, 256, 96000>>>(qp, kp, vp, att);
    GEMM64(att, cal_Wo, nullptr, nullptr, o1, RQ, 0);
    ln_kernel<<<lnG, 256>>>(o1, q, cal_ln1g, cal_ln1b, x, RQ);
    gemm_kernel<64,256><<<gQ, 256, 65536>>>(x,  cal_W1, cal_b1, nullptr, h1, RQ, 1);
    gemm_kernel<256,64><<<gQ, 256, 65536>>>(h1, cal_W2, cal_b2, nullptr, o1, RQ, 0);
    ln_kernel<<<lnG, 256>>>(o1, x, cal_ln2g, cal_ln2b, x2, RQ);

    // ---- MGAN decoder layers ----
    float* cur = x2;
    float* nxt = xn;
    for (int i = 0; i < 2; i++) {
        ln_kernel<<<lnG, 256>>>(cur, nullptr, m_ln_g + i*64, m_ln_b + i*64, qn, RQ);
        GEMM64(qn, m_fc1_W + i*4096, m_fc1_b + i*64, nullptr, t1, RQ, 2);  // sigmoid
        GEMM64(qn, m_fc2_W + i*4096, m_fc2_b + i*64, t1,      sg, RQ, 0);  // * t1
        GEMM64(sg,  m_Wq + i*4096, nullptr, nullptr, qp, RQ, 0);
        GEMM64(enc, m_Wk + i*4096, nullptr, nullptr, kp, RK, 0);
        GEMM64(enc, m_Wv + i*4096, nullptr, nullptr, vp, RK, 0);
        attn_kernel<true><<<agrid, 256, 96000>>>(qp, kp, vp, att);
        GEMM64(att, m_Wo + i*4096, nullptr, nullptr, o1, RQ, 0);
        ln_kernel<<<lnG, 256>>>(o1, sg, m_aln_g + i*64, m_aln_b + i*64, awg, RQ);
        glu_kernel<<<(RQ*Cc + 255) / 256, 256>>>(qn, sg, awg, nxt, RQ*Cc);
        float* tmp = cur; cur = nxt; nxt = tmp;
    }

    // ---- head ----
    head_kernel<<<(RQ + 255) / 256, 256>>>(cur, fc_W, fc_b, (float*)d_out, RQ);
}

// round 2
// speedup vs baseline: 1.1105x; 1.1105x over previous
#include <cuda_runtime.h>
#include <cstdint>

// Problem constants
#define Bq 4
#define LQ 3000
#define LKk 750
#define Cc 64
#define NHh 4
#define Ff 256
#define RQ (Bq*LQ)      // 12000
#define RK (Bq*LKk)     // 3000

// ---------------- scratch (static device globals) --------------------------
static __device__ float g_qp [RQ*Cc];
static __device__ float g_kp [RK*Cc];
static __device__ float g_vp [RK*Cc];
static __device__ float g_att[RQ*Cc];
static __device__ float g_x  [RQ*Cc];
static __device__ float g_h1 [RQ*Ff];
static __device__ float g_x2 [RQ*Cc];
static __device__ float g_qn [RQ*Cc];
static __device__ float g_sg [RQ*Cc];
static __device__ float g_xn [RQ*Cc];

// ---------------- GEMM: Y[rows,N] = act(X[rows,K] @ W[K,N] + bias) ---------
// act: 0=none, 1=relu
template<int K, int N>
__global__ __launch_bounds__(256)
void gemm_kernel(const float* __restrict__ X, const float* __restrict__ W,
                 const float* __restrict__ bias, float* __restrict__ Y,
                 int rows, int act)
{
    extern __shared__ float4 Ws4[];              // K*N/4 float4
    constexpr int C4 = N / 4;
    for (int i = threadIdx.x; i < K * C4; i += 256)
        Ws4[i] = reinterpret_cast<const float4*>(W)[i];
    __syncthreads();

    const int c4 = threadIdx.x % C4;
    const int rbase = blockIdx.x * 64;
    for (int rr = threadIdx.x / C4; rr < 64; rr += 256 / C4) {
        int row = rbase + rr;
        if (row >= rows) break;
        float ax = 0.f, ay = 0.f, az = 0.f, aw = 0.f;
        const float4* xrow = reinterpret_cast<const float4*>(X + (size_t)row * K);
#pragma unroll 8
        for (int k4 = 0; k4 < K / 4; k4++) {
            float4 xq = __ldg(&xrow[k4]);
            float4 w0 = Ws4[(k4*4+0)*C4 + c4];
            float4 w1 = Ws4[(k4*4+1)*C4 + c4];
            float4 w2 = Ws4[(k4*4+2)*C4 + c4];
            float4 w3 = Ws4[(k4*4+3)*C4 + c4];
            ax += xq.x*w0.x + xq.y*w1.x + xq.z*w2.x + xq.w*w3.x;
            ay += xq.x*w0.y + xq.y*w1.y + xq.z*w2.y + xq.w*w3.y;
            az += xq.x*w0.z + xq.y*w1.z + xq.z*w2.z + xq.w*w3.z;
            aw += xq.x*w0.w + xq.y*w1.w + xq.z*w2.w + xq.w*w3.w;
        }
        if (bias) {
            float4 bv = __ldg(&reinterpret_cast<const float4*>(bias)[c4]);
            ax += bv.x; ay += bv.y; az += bv.z; aw += bv.w;
        }
        if (act == 1) {
            ax = fmaxf(ax, 0.f); ay = fmaxf(ay, 0.f);
            az = fmaxf(az, 0.f); aw = fmaxf(aw, 0.f);
        }
        float4 o; o.x = ax; o.y = ay; o.z = az; o.w = aw;
        reinterpret_cast<float4*>(Y + (size_t)row * N)[c4] = o;
    }
}

// ---------------- dual-weight GEMM (K=64, N=64 each) -----------------------
// MODE 0: Y1 = X@Wa, Y2 = X@Wb   (K/V projections)
// MODE 1: Y1 = sigmoid(X@Wa + ba) * (X@Wb + bb)   (fc1*fc2 gate)
template<int MODE>
__global__ __launch_bounds__(256)
void gemm_dual_kernel(const float* __restrict__ X,
                      const float* __restrict__ Wa, const float* __restrict__ Wb,
                      const float* __restrict__ ba, const float* __restrict__ bb,
                      float* __restrict__ Y1, float* __restrict__ Y2, int rows)
{
    __shared__ float4 Wsa[64*16];
    __shared__ float4 Wsb[64*16];
    for (int i = threadIdx.x; i < 64*16; i += 256) {
        Wsa[i] = reinterpret_cast<const float4*>(Wa)[i];
        Wsb[i] = reinterpret_cast<const float4*>(Wb)[i];
    }
    __syncthreads();
    const int c4 = threadIdx.x & 15;
    const int rbase = blockIdx.x * 64;
    for (int rr = threadIdx.x >> 4; rr < 64; rr += 16) {
        int row = rbase + rr;
        if (row >= rows) break;
        float a0=0,a1=0,a2=0,a3=0, b0=0,b1=0,b2=0,b3=0;
        const float4* xr = reinterpret_cast<const float4*>(X + (size_t)row * 64);
#pragma unroll 8
        for (int k4 = 0; k4 < 16; k4++) {
            float4 xq = __ldg(&xr[k4]);
            float4 wa0 = Wsa[(k4*4+0)*16 + c4];
            float4 wa1 = Wsa[(k4*4+1)*16 + c4];
            float4 wa2 = Wsa[(k4*4+2)*16 + c4];
            float4 wa3 = Wsa[(k4*4+3)*16 + c4];
            a0 += xq.x*wa0.x + xq.y*wa1.x + xq.z*wa2.x + xq.w*wa3.x;
            a1 += xq.x*wa0.y + xq.y*wa1.y + xq.z*wa2.y + xq.w*wa3.y;
            a2 += xq.x*wa0.z + xq.y*wa1.z + xq.z*wa2.z + xq.w*wa3.z;
            a3 += xq.x*wa0.w + xq.y*wa1.w + xq.z*wa2.w + xq.w*wa3.w;
            float4 wb0 = Wsb[(k4*4+0)*16 + c4];
            float4 wb1 = Wsb[(k4*4+1)*16 + c4];
            float4 wb2 = Wsb[(k4*4+2)*16 + c4];
            float4 wb3 = Wsb[(k4*4+3)*16 + c4];
            b0 += xq.x*wb0.x + xq.y*wb1.x + xq.z*wb2.x + xq.w*wb3.x;
            b1 += xq.x*wb0.y + xq.y*wb1.y + xq.z*wb2.y + xq.w*wb3.y;
            b2 += xq.x*wb0.z + xq.y*wb1.z + xq.z*wb2.z + xq.w*wb3.z;
            b3 += xq.x*wb0.w + xq.y*wb1.w + xq.z*wb2.w + xq.w*wb3.w;
        }
        if (MODE == 0) {
            float4 o1v = {a0,a1,a2,a3}, o2v = {b0,b1,b2,b3};
            reinterpret_cast<float4*>(Y1 + (size_t)row * 64)[c4] = o1v;
            reinterpret_cast<float4*>(Y2 + (size_t)row * 64)[c4] = o2v;
        } else {
            float4 bav = __ldg(&reinterpret_cast<const float4*>(ba)[c4]);
            float4 bbv = __ldg(&reinterpret_cast<const float4*>(bb)[c4]);
            a0 += bav.x; a1 += bav.y; a2 += bav.z; a3 += bav.w;
            b0 += bbv.x; b1 += bbv.y; b2 += bbv.z; b3 += bbv.w;
            float4 o;
            o.x = b0 / (1.f + __expf(-a0));
            o.y = b1 / (1.f + __expf(-a1));
            o.z = b2 / (1.f + __expf(-a2));
            o.w = b3 / (1.f + __expf(-a3));
            reinterpret_cast<float4*>(Y1 + (size_t)row * 64)[c4] = o;
        }
    }
}

// ---------------- GEMM + residual + LayerNorm (+GLU) epilogue --------------
// Y = LN(X@W (+bias) + res) * g + be ; if GLU: Y = qn + sgv * sigmoid(that)
template<int K, bool GLU>
__global__ __launch_bounds__(256)
void gemm_ln_kernel(const float* __restrict__ X, const float* __restrict__ W,
                    const float* __restrict__ res, const float* __restrict__ bias,
                    const float* __restrict__ g, const float* __restrict__ be,
                    const float* __restrict__ qn, const float* __restrict__ sgv,
                    float* __restrict__ Y, int rows)
{
    extern __shared__ float4 Ws4[];              // K*16 float4
    for (int i = threadIdx.x; i < K * 16; i += 256)
        Ws4[i] = reinterpret_cast<const float4*>(W)[i];
    __syncthreads();

    const int c4 = threadIdx.x & 15;
    const int rbase = blockIdx.x * 64;
#pragma unroll 1
    for (int it = 0; it < 4; it++) {
        int row = rbase + (threadIdx.x >> 4) + it * 16;
        bool valid = row < rows;
        float ax = 0.f, ay = 0.f, az = 0.f, aw = 0.f;
        if (valid) {
            const float4* xrow = reinterpret_cast<const float4*>(X + (size_t)row * K);
#pragma unroll 8
            for (int k4 = 0; k4 < K / 4; k4++) {
                float4 xq = __ldg(&xrow[k4]);
                float4 w0 = Ws4[(k4*4+0)*16 + c4];
                float4 w1 = Ws4[(k4*4+1)*16 + c4];
                float4 w2 = Ws4[(k4*4+2)*16 + c4];
                float4 w3 = Ws4[(k4*4+3)*16 + c4];
                ax += xq.x*w0.x + xq.y*w1.x + xq.z*w2.x + xq.w*w3.x;
                ay += xq.x*w0.y + xq.y*w1.y + xq.z*w2.y + xq.w*w3.y;
                az += xq.x*w0.z + xq.y*w1.z + xq.z*w2.z + xq.w*w3.z;
                aw += xq.x*w0.w + xq.y*w1.w + xq.z*w2.w + xq.w*w3.w;
            }
            if (bias) {
                float4 bv = __ldg(&reinterpret_cast<const float4*>(bias)[c4]);
                ax += bv.x; ay += bv.y; az += bv.z; aw += bv.w;
            }
            float4 rv = reinterpret_cast<const float4*>(res + (size_t)row * 64)[c4];
            ax += rv.x; ay += rv.y; az += rv.z; aw += rv.w;
        }
        float s  = ax + ay + az + aw;
        float ss = ax*ax + ay*ay + az*az + aw*aw;
#pragma unroll
        for (int off = 1; off < 16; off <<= 1) {
            s  += __shfl_xor_sync(0xffffffffu, s,  off);
            ss += __shfl_xor_sync(0xffffffffu, ss, off);
        }
        float mean = s * (1.f/64.f);
        float rstd = rsqrtf(ss * (1.f/64.f) - mean * mean + 1e-6f);
        if (valid) {
            float4 gv = __ldg(&reinterpret_cast<const float4*>(g)[c4]);
            float4 bv = __ldg(&reinterpret_cast<const float4*>(be)[c4]);
            float4 o;
            o.x = (ax - mean) * rstd * gv.x + bv.x;
            o.y = (ay - mean) * rstd * gv.y + bv.y;
            o.z = (az - mean) * rstd * gv.z + bv.z;
            o.w = (aw - mean) * rstd * gv.w + bv.w;
            if (GLU) {
                float4 qv = reinterpret_cast<const float4*>(qn  + (size_t)row * 64)[c4];
                float4 sv = reinterpret_cast<const float4*>(sgv + (size_t)row * 64)[c4];
                o.x = qv.x + sv.x / (1.f + __expf(-o.x));
                o.y = qv.y + sv.y / (1.f + __expf(-o.y));
                o.z = qv.z + sv.z / (1.f + __expf(-o.z));
                o.w = qv.w + sv.w / (1.f + __expf(-o.w));
            }
            reinterpret_cast<float4*>(Y + (size_t)row * 64)[c4] = o;
        }
    }
}

// ---------------- plain attention: single-pass online softmax --------------
__global__ __launch_bounds__(256, 2)
void attn_plain_kernel(const float* __restrict__ qp, const float* __restrict__ kp,
                       const float* __restrict__ vp, float* __restrict__ outp)
{
    extern __shared__ float4 sKV[];  // [0,3000): K, [3000,6000): V
    const int b = blockIdx.y >> 2, h = blockIdx.y & 3;
    const float* kb = kp + ((size_t)b * LKk) * Cc + h * 16;
    const float* vb = vp + ((size_t)b * LKk) * Cc + h * 16;
    for (int idx = threadIdx.x; idx < LKk * 4; idx += 256) {
        int j = idx >> 2, d = idx & 3;
        sKV[idx]           = *reinterpret_cast<const float4*>(kb + (size_t)j * Cc + d * 4);
        sKV[idx + LKk * 4] = *reinterpret_cast<const float4*>(vb + (size_t)j * Cc + d * 4);
    }
    __syncthreads();

    int qi = blockIdx.x * 256 + threadIdx.x;
    if (qi >= LQ) return;
    const float* qr = qp + ((size_t)(b * LQ + qi)) * Cc + h * 16;
    float4 q0 = *reinterpret_cast<const float4*>(qr + 0);
    float4 q1 = *reinterpret_cast<const float4*>(qr + 4);
    float4 q2 = *reinterpret_cast<const float4*>(qr + 8);
    float4 q3 = *reinterpret_cast<const float4*>(qr + 12);
    const float sc = 0.25f;
    q0.x*=sc;q0.y*=sc;q0.z*=sc;q0.w*=sc; q1.x*=sc;q1.y*=sc;q1.z*=sc;q1.w*=sc;
    q2.x*=sc;q2.y*=sc;q2.z*=sc;q2.w*=sc; q3.x*=sc;q3.y*=sc;q3.z*=sc;q3.w*=sc;

    float m = -3.4e38f, l = 0.f;
    float4 o0 = {0,0,0,0}, o1v = {0,0,0,0}, o2 = {0,0,0,0}, o3 = {0,0,0,0};
    for (int j = 0; j < LKk; j++) {
        const float4* kj = &sKV[j * 4];
        float4 k0 = kj[0], k1 = kj[1], k2 = kj[2], k3 = kj[3];
        float s = q0.x*k0.x + q0.y*k0.y + q0.z*k0.z + q0.w*k0.w
                + q1.x*k1.x + q1.y*k1.y + q1.z*k1.z + q1.w*k1.w
                + q2.x*k2.x + q2.y*k2.y + q2.z*k2.z + q2.w*k2.w
                + q3.x*k3.x + q3.y*k3.y + q3.z*k3.z + q3.w*k3.w;
        float p;
        if (s > m) {
            float r = __expf(m - s);   // first iter: exp(-huge) = 0
            l *= r;
            o0.x*=r;o0.y*=r;o0.z*=r;o0.w*=r; o1v.x*=r;o1v.y*=r;o1v.z*=r;o1v.w*=r;
            o2.x*=r;o2.y*=r;o2.z*=r;o2.w*=r; o3.x*=r;o3.y*=r;o3.z*=r;o3.w*=r;
            m = s; p = 1.f;
        } else {
            p = __expf(s - m);
        }
        l += p;
        const float4* vj = &sKV[LKk*4 + j*4];
        float4 v0 = vj[0], v1 = vj[1], v2 = vj[2], v3 = vj[3];
        o0.x += p*v0.x; o0.y += p*v0.y; o0.z += p*v0.z; o0.w += p*v0.w;
        o1v.x += p*v1.x; o1v.y += p*v1.y; o1v.z += p*v1.z; o1v.w += p*v1.w;
        o2.x += p*v2.x; o2.y += p*v2.y; o2.z += p*v2.z; o2.w += p*v2.w;
        o3.x += p*v3.x; o3.y += p*v3.y; o3.z += p*v3.z; o3.w += p*v3.w;
    }
    float inv = 1.f / l;
    float* orow = outp + ((size_t)(b * LQ + qi)) * Cc + h * 16;
    float4 w0 = {o0.x*inv, o0.y*inv, o0.z*inv, o0.w*inv};
    float4 w1 = {o1v.x*inv, o1v.y*inv, o1v.z*inv, o1v.w*inv};
    float4 w2 = {o2.x*inv, o2.y*inv, o2.z*inv, o2.w*inv};
    float4 w3 = {o3.x*inv, o3.y*inv, o3.z*inv, o3.w*inv};
    *reinterpret_cast<float4*>(orow + 0)  = w0;
    *reinterpret_cast<float4*>(orow + 4)  = w1;
    *reinterpret_cast<float4*>(orow + 8)  = w2;
    *reinterpret_cast<float4*>(orow + 12) = w3;
}

// ---------------- AWG top-16 attention -------------------------------------
// Pass 1: branch-free FMIN/FMAX top-16 merge (values only).
// Pass 2: rescan, gate s>=thr (identical semantics to reference incl. ties),
//         V gathered from global (L2) — only ~16 survivors per query.
__global__ __launch_bounds__(256, 3)
void attn_topk_kernel(const float* __restrict__ qp, const float* __restrict__ kp,
                      const float* __restrict__ vp, float* __restrict__ outp)
{
    extern __shared__ float4 sK[];  // 750*4 float4 = 48 KB
    const int b = blockIdx.y >> 2, h = blockIdx.y & 3;
    const float* kb = kp + ((size_t)b * LKk) * Cc + h * 16;
    const float* vb = vp + ((size_t)b * LKk) * Cc + h * 16;
    for (int idx = threadIdx.x; idx < LKk * 4; idx += 256) {
        int j = idx >> 2, d = idx & 3;
        sK[idx] = *reinterpret_cast<const float4*>(kb + (size_t)j * Cc + d * 4);
    }
    __syncthreads();

    int qi = blockIdx.x * 256 + threadIdx.x;
    if (qi >= LQ) return;
    const float* qr = qp + ((size_t)(b * LQ + qi)) * Cc + h * 16;
    float4 q0 = *reinterpret_cast<const float4*>(qr + 0);
    float4 q1 = *reinterpret_cast<const float4*>(qr + 4);
    float4 q2 = *reinterpret_cast<const float4*>(qr + 8);
    float4 q3 = *reinterpret_cast<const float4*>(qr + 12);
    const float sc = 0.25f;
    q0.x*=sc;q0.y*=sc;q0.z*=sc;q0.w*=sc; q1.x*=sc;q1.y*=sc;q1.z*=sc;q1.w*=sc;
    q2.x*=sc;q2.y*=sc;q2.z*=sc;q2.w*=sc; q3.x*=sc;q3.y*=sc;q3.z*=sc;q3.w*=sc;

    float t[16];
#pragma unroll
    for (int k = 0; k < 16; k++) t[k] = -3.4e38f;

    // pass 1: maintain ascending top-16 via dense min/max merge
    for (int j = 0; j < LKk; j++) {
        const float4* kj = &sK[j * 4];
        float4 k0 = kj[0], k1 = kj[1], k2 = kj[2], k3 = kj[3];
        float s = q0.x*k0.x + q0.y*k0.y + q0.z*k0.z + q0.w*k0.w
                + q1.x*k1.x + q1.y*k1.y + q1.z*k1.z + q1.w*k1.w
                + q2.x*k2.x + q2.y*k2.y + q2.z*k2.z + q2.w*k2.w
                + q3.x*k3.x + q3.y*k3.y + q3.z*k3.z + q3.w*k3.w;
#pragma unroll
        for (int u = 0; u < 15; u++)
            t[u] = fminf(t[u+1], fmaxf(t[u], s));
        t[15] = fmaxf(t[15], s);
    }
    const float thr = t[0];
    const float m   = t[15];

    // pass 2: rescan, gate, accumulate V from global
    float l = 0.f;
    float4 o0 = {0,0,0,0}, o1v = {0,0,0,0}, o2 = {0,0,0,0}, o3 = {0,0,0,0};
    for (int j = 0; j < LKk; j++) {
        const float4* kj = &sK[j * 4];
        float4 k0 = kj[0], k1 = kj[1], k2 = kj[2], k3 = kj[3];
        float s = q0.x*k0.x + q0.y*k0.y + q0.z*k0.z + q0.w*k0.w
                + q1.x*k1.x + q1.y*k1.y + q1.z*k1.z + q1.w*k1.w
                + q2.x*k2.x + q2.y*k2.y + q2.z*k2.z + q2.w*k2.w
                + q3.x*k3.x + q3.y*k3.y + q3.z*k3.z + q3.w*k3.w;
        if (s >= thr) {
            float p = __expf(s - m);
            l += p;
            const float4* vr = reinterpret_cast<const float4*>(vb + (size_t)j * Cc);
            float4 v0 = __ldg(&vr[0]), v1 = __ldg(&vr[1]);
            float4 v2 = __ldg(&vr[2]), v3 = __ldg(&vr[3]);
            o0.x += p*v0.x; o0.y += p*v0.y; o0.z += p*v0.z; o0.w += p*v0.w;
            o1v.x += p*v1.x; o1v.y += p*v1.y; o1v.z += p*v1.z; o1v.w += p*v1.w;
            o2.x += p*v2.x; o2.y += p*v2.y; o2.z += p*v2.z; o2.w += p*v2.w;
            o3.x += p*v3.x; o3.y += p*v3.y; o3.z += p*v3.z; o3.w += p*v3.w;
        }
    }
    float inv = 1.f / l;
    float* orow = outp + ((size_t)(b * LQ + qi)) * Cc + h * 16;
    float4 w0 = {o0.x*inv, o0.y*inv, o0.z*inv, o0.w*inv};
    float4 w1 = {o1v.x*inv, o1v.y*inv, o1v.z*inv, o1v.w*inv};
    float4 w2 = {o2.x*inv, o2.y*inv, o2.z*inv, o2.w*inv};
    float4 w3 = {o3.x*inv, o3.y*inv, o3.z*inv, o3.w*inv};
    *reinterpret_cast<float4*>(orow + 0)  = w0;
    *reinterpret_cast<float4*>(orow + 4)  = w1;
    *reinterpret_cast<float4*>(orow + 8)  = w2;
    *reinterpret_cast<float4*>(orow + 12) = w3;
}

// ---------------- standalone LayerNorm (for qn) -----------------------------
__global__ __launch_bounds__(256)
void ln_kernel(const float* __restrict__ a, const float* __restrict__ g,
               const float* __restrict__ be, float* __restrict__ y, int rows)
{
    int w = (blockIdx.x * 256 + threadIdx.x) >> 5;
    int lane = threadIdx.x & 31;
    if (w >= rows) return;
    const float* ar = a + (size_t)w * Cc;
    float v0 = ar[lane], v1 = ar[lane + 32];
    float s = v0 + v1, ss = v0*v0 + v1*v1;
#pragma unroll
    for (int o = 16; o; o >>= 1) {
        s  += __shfl_xor_sync(0xffffffffu, s, o);
        ss += __shfl_xor_sync(0xffffffffu, ss, o);
    }
    float mean = s * (1.f/64.f);
    float rstd = rsqrtf(ss * (1.f/64.f) - mean * mean + 1e-6f);
    y[(size_t)w*Cc + lane]      = (v0 - mean) * rstd * g[lane]      + be[lane];
    y[(size_t)w*Cc + lane + 32] = (v1 - mean) * rstd * g[lane + 32] + be[lane + 32];
}

// ---------------- head: out = sigmoid(x @ fcW + fcb) ------------------------
__global__ __launch_bounds__(256)
void head_kernel(const float* __restrict__ x, const float* __restrict__ fw,
                 const float* __restrict__ fb, float* __restrict__ out, int rows)
{
    __shared__ float w[Cc];
    __shared__ float b0;
    if (threadIdx.x < Cc) w[threadIdx.x] = fw[threadIdx.x];
    if (threadIdx.x == 0) b0 = fb[0];
    __syncthreads();
    int r = blockIdx.x * 256 + threadIdx.x;
    if (r >= rows) return;
    const float4* xr = reinterpret_cast<const float4*>(x + (size_t)r * Cc);
    float acc = b0;
#pragma unroll
    for (int k4 = 0; k4 < 16; k4++) {
        float4 xv = __ldg(&xr[k4]);
        acc += xv.x * w[k4*4+0] + xv.y * w[k4*4+1] + xv.z * w[k4*4+2] + xv.w * w[k4*4+3];
    }
    out[r] = 1.f / (1.f + __expf(-acc));
}

// ---------------- host orchestration ----------------------------------------
extern "C" void kernel_launch(void* const* d_in, const int* in_sizes, int n_in,
                              void* d_out, int out_size)
{
    const float* q        = (const float*)d_in[0];
    const float* enc      = (const float*)d_in[1];
    const float* cal_Wq   = (const float*)d_in[2];
    const float* cal_Wk   = (const float*)d_in[3];
    const float* cal_Wv   = (const float*)d_in[4];
    const float* cal_Wo   = (const float*)d_in[5];
    const float* cal_ln1g = (const float*)d_in[6];
    const float* cal_ln1b = (const float*)d_in[7];
    const float* cal_W1   = (const float*)d_in[8];
    const float* cal_b1   = (const float*)d_in[9];
    const float* cal_W2   = (const float*)d_in[10];
    const float* cal_b2   = (const float*)d_in[11];
    const float* cal_ln2g = (const float*)d_in[12];
    const float* cal_ln2b = (const float*)d_in[13];
    const float* m_ln_g   = (const float*)d_in[14];
    const float* m_ln_b   = (const float*)d_in[15];
    const float* m_fc1_W  = (const float*)d_in[16];
    const float* m_fc1_b  = (const float*)d_in[17];
    const float* m_fc2_W  = (const float*)d_in[18];
    const float* m_fc2_b  = (const float*)d_in[19];
    const float* m_Wq     = (const float*)d_in[20];
    const float* m_Wk     = (const float*)d_in[21];
    const float* m_Wv     = (const float*)d_in[22];
    const float* m_Wo     = (const float*)d_in[23];
    const float* m_aln_g  = (const float*)d_in[24];
    const float* m_aln_b  = (const float*)d_in[25];
    const float* fc_W     = (const float*)d_in[26];
    const float* fc_b     = (const float*)d_in[27];

    float *qp, *kp, *vp, *att, *x, *h1, *x2, *qn, *sg, *xn;
    cudaGetSymbolAddress((void**)&qp,  g_qp);
    cudaGetSymbolAddress((void**)&kp,  g_kp);
    cudaGetSymbolAddress((void**)&vp,  g_vp);
    cudaGetSymbolAddress((void**)&att, g_att);
    cudaGetSymbolAddress((void**)&x,   g_x);
    cudaGetSymbolAddress((void**)&h1,  g_h1);
    cudaGetSymbolAddress((void**)&x2,  g_x2);
    cudaGetSymbolAddress((void**)&qn,  g_qn);
    cudaGetSymbolAddress((void**)&sg,  g_sg);
    cudaGetSymbolAddress((void**)&xn,  g_xn);

    cudaFuncSetAttribute(attn_plain_kernel, cudaFuncAttributeMaxDynamicSharedMemorySize, 96000);
    cudaFuncSetAttribute(attn_topk_kernel,  cudaFuncAttributeMaxDynamicSharedMemorySize, 48000);
    cudaFuncSetAttribute((gemm_kernel<64,256>),   cudaFuncAttributeMaxDynamicSharedMemorySize, 65536);
    cudaFuncSetAttribute((gemm_ln_kernel<256,false>), cudaFuncAttributeMaxDynamicSharedMemorySize, 65536);

    const int smem64 = 64 * 64 * 4;          // 16 KB
    const int gQ = (RQ + 63) / 64;           // 188
    const int gK = (RK + 63) / 64;           // 47
    const int lnG = (RQ * 32 + 255) / 256;   // 1500
    dim3 agrid((LQ + 255) / 256, Bq * NHh);  // (12, 16)

    // ---- cross_attn_layer ----
    gemm_kernel<64,64><<<gQ, 256, smem64>>>(q, cal_Wq, nullptr, qp, RQ, 0);
    gemm_dual_kernel<0><<<gK, 256>>>(enc, cal_Wk, cal_Wv, nullptr, nullptr, kp, vp, RK);
    attn_plain_kernel<<<agrid, 256, 96000>>>(qp, kp, vp, att);
    gemm_ln_kernel<64,false><<<gQ, 256, smem64>>>(att, cal_Wo, q, nullptr,
                                                  cal_ln1g, cal_ln1b, nullptr, nullptr, x, RQ);
    gemm_kernel<64,256><<<gQ, 256, 65536>>>(x, cal_W1, cal_b1, h1, RQ, 1);
    gemm_ln_kernel<256,false><<<gQ, 256, 65536>>>(h1, cal_W2, x, cal_b2,
                                                  cal_ln2g, cal_ln2b, nullptr, nullptr, x2, RQ);

    // ---- MGAN decoder layers ----
    float* cur = x2;
    float* nxt = xn;
    for (int i = 0; i < 2; i++) {
        ln_kernel<<<lnG, 256>>>(cur, m_ln_g + i*64, m_ln_b + i*64, qn, RQ);
        gemm_dual_kernel<1><<<gQ, 256>>>(qn, m_fc1_W + i*4096, m_fc2_W + i*4096,
                                         m_fc1_b + i*64, m_fc2_b + i*64, sg, nullptr, RQ);
        gemm_kernel<64,64><<<gQ, 256, smem64>>>(sg, m_Wq + i*4096, nullptr, qp, RQ, 0);
        gemm_dual_kernel<0><<<gK, 256>>>(enc, m_Wk + i*4096, m_Wv + i*4096,
                                         nullptr, nullptr, kp, vp, RK);
        attn_topk_kernel<<<agrid, 256, 48000>>>(qp, kp, vp, att);
        gemm_ln_kernel<64,true><<<gQ, 256, smem64>>>(att, m_Wo + i*4096, sg, nullptr,
                                                     m_aln_g + i*64, m_aln_b + i*64,
                                                     qn, sg, nxt, RQ);
        float* tmp = cur; cur = nxt; nxt = tmp;
    }

    // ---- head ----
    head_kernel<<<(RQ + 255) / 256, 256>>>(cur, fc_W, fc_b, (float*)d_out, RQ);
}

// round 3
// speedup vs baseline: 1.6099x; 1.4498x over previous
#include <cuda_runtime.h>
#include <cstdint>

// Problem constants
#define Bq 4
#define LQ 3000
#define LKk 750
#define LKH 375          // keys per half
#define Cc 64
#define NHh 4
#define Ff 256
#define RQ (Bq*LQ)       // 12000
#define RK (Bq*LKk)      // 3000
#define NQH (Bq*NHh*LQ)  // 48000 (b,h,q) rows

// ---------------- scratch (static device globals) --------------------------
static __device__ float g_qp [RQ*Cc];
static __device__ float g_kp [RK*Cc];
static __device__ float g_vp [RK*Cc];
static __device__ float g_att[RQ*Cc];
static __device__ float g_x  [RQ*Cc];
static __device__ float g_h1 [RQ*Ff];
static __device__ float g_x2 [RQ*Cc];
static __device__ float g_qnA[RQ*Cc];
static __device__ float g_qnB[RQ*Cc];
static __device__ float g_sg [RQ*Cc];
static __device__ float g_xn [RQ*Cc];
// attention partials
static __device__ float g_pm [NQH*2];
static __device__ float g_pl [NQH*2];
static __device__ float g_po [NQH*2*16];
static __device__ float g_tp [NQH*2*16];
static __device__ float g_thrm[NQH*2];

// ---------------- generic projection GEMM -----------------------------------
// Y[rows,N] = act(X[rows,K] @ W[K,N] + bias); RPT rows per thread (interleaved)
// act: 0=none, 1=relu
template<int K, int N, int RPT, int ACT>
__global__ __launch_bounds__(256)
void proj_kernel(const float* __restrict__ X, const float* __restrict__ W,
                 const float* __restrict__ bias, float* __restrict__ Y, int rows)
{
    extern __shared__ float4 Ws[];               // K * N/4 float4
    constexpr int C4 = N / 4;
    constexpr int RT = 256 / C4;
    for (int i = threadIdx.x; i < K * C4; i += 256)
        Ws[i] = reinterpret_cast<const float4*>(W)[i];
    __syncthreads();

    const int c4 = threadIdx.x & (C4 - 1);
    const int rt = threadIdx.x / C4;
    const int base = blockIdx.x * (RT * RPT);

    float4 acc[RPT];
    const float4* xr[RPT];
    int  rowv[RPT];
    bool valid[RPT];
#pragma unroll
    for (int i = 0; i < RPT; i++) {
        acc[i] = make_float4(0.f, 0.f, 0.f, 0.f);
        int r = base + rt + i * RT;
        valid[i] = r < rows;
        rowv[i] = r;
        xr[i] = reinterpret_cast<const float4*>(X + (size_t)(valid[i] ? r : 0) * K);
    }
#pragma unroll
    for (int k4 = 0; k4 < K / 4; k4++) {
        float4 xq[RPT];
#pragma unroll
        for (int i = 0; i < RPT; i++) xq[i] = __ldg(&xr[i][k4]);
        float4 w0 = Ws[(k4*4+0)*C4 + c4];
        float4 w1 = Ws[(k4*4+1)*C4 + c4];
        float4 w2 = Ws[(k4*4+2)*C4 + c4];
        float4 w3 = Ws[(k4*4+3)*C4 + c4];
#pragma unroll
        for (int i = 0; i < RPT; i++) {
            acc[i].x += xq[i].x*w0.x + xq[i].y*w1.x + xq[i].z*w2.x + xq[i].w*w3.x;
            acc[i].y += xq[i].x*w0.y + xq[i].y*w1.y + xq[i].z*w2.y + xq[i].w*w3.y;
            acc[i].z += xq[i].x*w0.z + xq[i].y*w1.z + xq[i].z*w2.z + xq[i].w*w3.z;
            acc[i].w += xq[i].x*w0.w + xq[i].y*w1.w + xq[i].z*w2.w + xq[i].w*w3.w;
        }
    }
#pragma unroll
    for (int i = 0; i < RPT; i++) {
        if (!valid[i]) continue;
        float4 o = acc[i];
        if (bias) {
            float4 bv = __ldg(&reinterpret_cast<const float4*>(bias)[c4]);
            o.x += bv.x; o.y += bv.y; o.z += bv.z; o.w += bv.w;
        }
        if (ACT == 1) {
            o.x = fmaxf(o.x, 0.f); o.y = fmaxf(o.y, 0.f);
            o.z = fmaxf(o.z, 0.f); o.w = fmaxf(o.w, 0.f);
        }
        reinterpret_cast<float4*>(Y + (size_t)rowv[i] * N)[c4] = o;
    }
}

// ---------------- dual-weight GEMM (K=64, N=64 each) ------------------------
// MODE 0: Y1 = X@Wa, Y2 = X@Wb      MODE 1: Y1 = sigmoid(X@Wa+ba)*(X@Wb+bb)
template<int MODE, int RPT>
__global__ __launch_bounds__(256)
void dual_kernel(const float* __restrict__ X,
                 const float* __restrict__ Wa, const float* __restrict__ Wb,
                 const float* __restrict__ ba, const float* __restrict__ bb,
                 float* __restrict__ Y1, float* __restrict__ Y2, int rows)
{
    __shared__ float4 Wsa[64*16];
    __shared__ float4 Wsb[64*16];
    for (int i = threadIdx.x; i < 64*16; i += 256) {
        Wsa[i] = reinterpret_cast<const float4*>(Wa)[i];
        Wsb[i] = reinterpret_cast<const float4*>(Wb)[i];
    }
    __syncthreads();
    const int c4 = threadIdx.x & 15;
    const int rt = threadIdx.x >> 4;
    const int base = blockIdx.x * (16 * RPT);

    float4 aacc[RPT], bacc[RPT];
    const float4* xr[RPT];
    int rowv[RPT]; bool valid[RPT];
#pragma unroll
    for (int i = 0; i < RPT; i++) {
        aacc[i] = make_float4(0,0,0,0); bacc[i] = make_float4(0,0,0,0);
        int r = base + rt + i * 16;
        valid[i] = r < rows; rowv[i] = r;
        xr[i] = reinterpret_cast<const float4*>(X + (size_t)(valid[i] ? r : 0) * 64);
    }
#pragma unroll
    for (int k4 = 0; k4 < 16; k4++) {
        float4 xq[RPT];
#pragma unroll
        for (int i = 0; i < RPT; i++) xq[i] = __ldg(&xr[i][k4]);
        float4 wa0 = Wsa[(k4*4+0)*16+c4], wa1 = Wsa[(k4*4+1)*16+c4];
        float4 wa2 = Wsa[(k4*4+2)*16+c4], wa3 = Wsa[(k4*4+3)*16+c4];
        float4 wb0 = Wsb[(k4*4+0)*16+c4], wb1 = Wsb[(k4*4+1)*16+c4];
        float4 wb2 = Wsb[(k4*4+2)*16+c4], wb3 = Wsb[(k4*4+3)*16+c4];
#pragma unroll
        for (int i = 0; i < RPT; i++) {
            aacc[i].x += xq[i].x*wa0.x + xq[i].y*wa1.x + xq[i].z*wa2.x + xq[i].w*wa3.x;
            aacc[i].y += xq[i].x*wa0.y + xq[i].y*wa1.y + xq[i].z*wa2.y + xq[i].w*wa3.y;
            aacc[i].z += xq[i].x*wa0.z + xq[i].y*wa1.z + xq[i].z*wa2.z + xq[i].w*wa3.z;
            aacc[i].w += xq[i].x*wa0.w + xq[i].y*wa1.w + xq[i].z*wa2.w + xq[i].w*wa3.w;
            bacc[i].x += xq[i].x*wb0.x + xq[i].y*wb1.x + xq[i].z*wb2.x + xq[i].w*wb3.x;
            bacc[i].y += xq[i].x*wb0.y + xq[i].y*wb1.y + xq[i].z*wb2.y + xq[i].w*wb3.y;
            bacc[i].z += xq[i].x*wb0.z + xq[i].y*wb1.z + xq[i].z*wb2.z + xq[i].w*wb3.z;
            bacc[i].w += xq[i].x*wb0.w + xq[i].y*wb1.w + xq[i].z*wb2.w + xq[i].w*wb3.w;
        }
    }
#pragma unroll
    for (int i = 0; i < RPT; i++) {
        if (!valid[i]) continue;
        if (MODE == 0) {
            reinterpret_cast<float4*>(Y1 + (size_t)rowv[i]*64)[c4] = aacc[i];
            reinterpret_cast<float4*>(Y2 + (size_t)rowv[i]*64)[c4] = bacc[i];
        } else {
            float4 bav = __ldg(&reinterpret_cast<const float4*>(ba)[c4]);
            float4 bbv = __ldg(&reinterpret_cast<const float4*>(bb)[c4]);
            float4 o;
            o.x = (bacc[i].x + bbv.x) / (1.f + __expf(-(aacc[i].x + bav.x)));
            o.y = (bacc[i].y + bbv.y) / (1.f + __expf(-(aacc[i].y + bav.y)));
            o.z = (bacc[i].z + bbv.z) / (1.f + __expf(-(aacc[i].z + bav.z)));
            o.w = (bacc[i].w + bbv.w) / (1.f + __expf(-(aacc[i].w + bav.w)));
            reinterpret_cast<float4*>(Y1 + (size_t)rowv[i]*64)[c4] = o;
        }
    }
}

// ---------------- GEMM + residual + LN (+GLU) (+LN2) (+head) ----------------
// y  = LN(X@W (+bias) + res)*g + be
// if qn:   y = qn + sgv * sigmoid(y)        (GLU combine)
// if g2:   Y2 = LN(y)*g2 + b2               (fused next-layer LN)
// if fw:   headout[row] = sigmoid(y . fw + fb)
template<int K>
__global__ __launch_bounds__(256)
void gemm_ln_kernel(const float* __restrict__ X, const float* __restrict__ W,
                    const float* __restrict__ res, const float* __restrict__ bias,
                    const float* __restrict__ g, const float* __restrict__ be,
                    const float* __restrict__ qn, const float* __restrict__ sgv,
                    const float* __restrict__ g2, const float* __restrict__ b2,
                    const float* __restrict__ fw, const float* __restrict__ fb,
                    float* __restrict__ Y, float* __restrict__ Y2,
                    float* __restrict__ headout, int rows)
{
    extern __shared__ float4 Ws[];               // K*16 float4
    for (int i = threadIdx.x; i < K * 16; i += 256)
        Ws[i] = reinterpret_cast<const float4*>(W)[i];
    __syncthreads();

    const int c4 = threadIdx.x & 15;
    const int rt = threadIdx.x >> 4;
    const int base = blockIdx.x * 32;

    float4 acc[2];
    const float4* xr[2];
    int rowv[2];
#pragma unroll
    for (int i = 0; i < 2; i++) {
        acc[i] = make_float4(0,0,0,0);
        rowv[i] = base + rt + i * 16;             // rows always == RQ (exact)
        xr[i] = reinterpret_cast<const float4*>(X + (size_t)rowv[i] * K);
    }
#pragma unroll
    for (int k4 = 0; k4 < K / 4; k4++) {
        float4 xq[2];
#pragma unroll
        for (int i = 0; i < 2; i++) xq[i] = __ldg(&xr[i][k4]);
        float4 w0 = Ws[(k4*4+0)*16 + c4];
        float4 w1 = Ws[(k4*4+1)*16 + c4];
        float4 w2 = Ws[(k4*4+2)*16 + c4];
        float4 w3 = Ws[(k4*4+3)*16 + c4];
#pragma unroll
        for (int i = 0; i < 2; i++) {
            acc[i].x += xq[i].x*w0.x + xq[i].y*w1.x + xq[i].z*w2.x + xq[i].w*w3.x;
            acc[i].y += xq[i].x*w0.y + xq[i].y*w1.y + xq[i].z*w2.y + xq[i].w*w3.y;
            acc[i].z += xq[i].x*w0.z + xq[i].y*w1.z + xq[i].z*w2.z + xq[i].w*w3.z;
            acc[i].w += xq[i].x*w0.w + xq[i].y*w1.w + xq[i].z*w2.w + xq[i].w*w3.w;
        }
    }
    float4 gv = __ldg(&reinterpret_cast<const float4*>(g)[c4]);
    float4 bv = __ldg(&reinterpret_cast<const float4*>(be)[c4]);
#pragma unroll
    for (int i = 0; i < 2; i++) {
        int row = rowv[i];
        float4 o = acc[i];
        if (bias) {
            float4 b4 = __ldg(&reinterpret_cast<const float4*>(bias)[c4]);
            o.x += b4.x; o.y += b4.y; o.z += b4.z; o.w += b4.w;
        }
        float4 rv = reinterpret_cast<const float4*>(res + (size_t)row * 64)[c4];
        o.x += rv.x; o.y += rv.y; o.z += rv.z; o.w += rv.w;
        float s  = o.x + o.y + o.z + o.w;
        float ss = o.x*o.x + o.y*o.y + o.z*o.z + o.w*o.w;
#pragma unroll
        for (int off = 1; off < 16; off <<= 1) {
            s  += __shfl_xor_sync(0xffffffffu, s,  off);
            ss += __shfl_xor_sync(0xffffffffu, ss, off);
        }
        float mean = s * (1.f/64.f);
        float rstd = rsqrtf(ss * (1.f/64.f) - mean * mean + 1e-6f);
        o.x = (o.x - mean) * rstd * gv.x + bv.x;
        o.y = (o.y - mean) * rstd * gv.y + bv.y;
        o.z = (o.z - mean) * rstd * gv.z + bv.z;
        o.w = (o.w - mean) * rstd * gv.w + bv.w;
        if (qn) {
            float4 qv = reinterpret_cast<const float4*>(qn  + (size_t)row * 64)[c4];
            float4 sv = reinterpret_cast<const float4*>(sgv + (size_t)row * 64)[c4];
            o.x = qv.x + sv.x / (1.f + __expf(-o.x));
            o.y = qv.y + sv.y / (1.f + __expf(-o.y));
            o.z = qv.z + sv.z / (1.f + __expf(-o.z));
            o.w = qv.w + sv.w / (1.f + __expf(-o.w));
        }
        reinterpret_cast<float4*>(Y + (size_t)row * 64)[c4] = o;
        if (g2) {
            float s2  = o.x + o.y + o.z + o.w;
            float ss2 = o.x*o.x + o.y*o.y + o.z*o.z + o.w*o.w;
#pragma unroll
            for (int off = 1; off < 16; off <<= 1) {
                s2  += __shfl_xor_sync(0xffffffffu, s2,  off);
                ss2 += __shfl_xor_sync(0xffffffffu, ss2, off);
            }
            float mean2 = s2 * (1.f/64.f);
            float rstd2 = rsqrtf(ss2 * (1.f/64.f) - mean2 * mean2 + 1e-6f);
            float4 g2v = __ldg(&reinterpret_cast<const float4*>(g2)[c4]);
            float4 b2v = __ldg(&reinterpret_cast<const float4*>(b2)[c4]);
            float4 y2;
            y2.x = (o.x - mean2) * rstd2 * g2v.x + b2v.x;
            y2.y = (o.y - mean2) * rstd2 * g2v.y + b2v.y;
            y2.z = (o.z - mean2) * rstd2 * g2v.z + b2v.z;
            y2.w = (o.w - mean2) * rstd2 * g2v.w + b2v.w;
            reinterpret_cast<float4*>(Y2 + (size_t)row * 64)[c4] = y2;
        }
        if (fw) {
            float4 wv = __ldg(&reinterpret_cast<const float4*>(fw)[c4]);
            float d = o.x*wv.x + o.y*wv.y + o.z*wv.z + o.w*wv.w;
#pragma unroll
            for (int off = 1; off < 16; off <<= 1)
                d += __shfl_xor_sync(0xffffffffu, d, off);
            if (c4 == 0)
                headout[row] = 1.f / (1.f + __expf(-(d + __ldg(fb))));
        }
    }
}

// ---------------- plain attention, split-K half: partial (m,l,o) ------------
__global__ __launch_bounds__(256, 3)
void attn_plain_part(const float* __restrict__ qp, const float* __restrict__ kp,
                     const float* __restrict__ vp,
                     float* __restrict__ pm, float* __restrict__ pl,
                     float* __restrict__ po)
{
    extern __shared__ float4 sKV[];  // [0,1500): K half, [1500,3000): V half
    const int bh = blockIdx.y >> 1, half = blockIdx.y & 1;
    const int b = bh >> 2, h = bh & 3;
    const int j0 = half * LKH;
    const float* kb = kp + ((size_t)(b * LKk + j0)) * Cc + h * 16;
    const float* vb = vp + ((size_t)(b * LKk + j0)) * Cc + h * 16;
    for (int idx = threadIdx.x; idx < LKH * 4; idx += 256) {
        int j = idx >> 2, d = idx & 3;
        sKV[idx]           = *reinterpret_cast<const float4*>(kb + (size_t)j * Cc + d * 4);
        sKV[idx + LKH * 4] = *reinterpret_cast<const float4*>(vb + (size_t)j * Cc + d * 4);
    }
    __syncthreads();

    int qi = blockIdx.x * 256 + threadIdx.x;
    if (qi >= LQ) return;
    const float* qr = qp + ((size_t)(b * LQ + qi)) * Cc + h * 16;
    float4 q0 = *reinterpret_cast<const float4*>(qr + 0);
    float4 q1 = *reinterpret_cast<const float4*>(qr + 4);
    float4 q2 = *reinterpret_cast<const float4*>(qr + 8);
    float4 q3 = *reinterpret_cast<const float4*>(qr + 12);
    const float sc = 0.25f;
    q0.x*=sc;q0.y*=sc;q0.z*=sc;q0.w*=sc; q1.x*=sc;q1.y*=sc;q1.z*=sc;q1.w*=sc;
    q2.x*=sc;q2.y*=sc;q2.z*=sc;q2.w*=sc; q3.x*=sc;q3.y*=sc;q3.z*=sc;q3.w*=sc;

    float m = -3.4e38f, l = 0.f;
    float4 o0 = {0,0,0,0}, o1v = {0,0,0,0}, o2 = {0,0,0,0}, o3 = {0,0,0,0};
    for (int j = 0; j < LKH; j++) {
        const float4* kj = &sKV[j * 4];
        float4 k0 = kj[0], k1 = kj[1], k2 = kj[2], k3 = kj[3];
        float s = q0.x*k0.x + q0.y*k0.y + q0.z*k0.z + q0.w*k0.w
                + q1.x*k1.x + q1.y*k1.y + q1.z*k1.z + q1.w*k1.w
                + q2.x*k2.x + q2.y*k2.y + q2.z*k2.z + q2.w*k2.w
                + q3.x*k3.x + q3.y*k3.y + q3.z*k3.z + q3.w*k3.w;
        float p;
        if (s > m) {
            float r = __expf(m - s);
            l *= r;
            o0.x*=r;o0.y*=r;o0.z*=r;o0.w*=r; o1v.x*=r;o1v.y*=r;o1v.z*=r;o1v.w*=r;
            o2.x*=r;o2.y*=r;o2.z*=r;o2.w*=r; o3.x*=r;o3.y*=r;o3.z*=r;o3.w*=r;
            m = s; p = 1.f;
        } else {
            p = __expf(s - m);
        }
        l += p;
        const float4* vj = &sKV[LKH*4 + j*4];
        float4 v0 = vj[0], v1 = vj[1], v2 = vj[2], v3 = vj[3];
        o0.x += p*v0.x; o0.y += p*v0.y; o0.z += p*v0.z; o0.w += p*v0.w;
        o1v.x += p*v1.x; o1v.y += p*v1.y; o1v.z += p*v1.z; o1v.w += p*v1.w;
        o2.x += p*v2.x; o2.y += p*v2.y; o2.z += p*v2.z; o2.w += p*v2.w;
        o3.x += p*v3.x; o3.y += p*v3.y; o3.z += p*v3.z; o3.w += p*v3.w;
    }
    size_t idx = (size_t)bh * LQ + qi;
    pm[idx*2 + half] = m;
    pl[idx*2 + half] = l;
    float4* pov = reinterpret_cast<float4*>(po + (idx*2 + half) * 16);
    pov[0] = o0; pov[1] = o1v; pov[2] = o2; pov[3] = o3;
}

// combine plain partials -> att[b,q,h*16]
__global__ __launch_bounds__(256)
void attn_plain_combine(const float* __restrict__ pm, const float* __restrict__ pl,
                        const float* __restrict__ po, float* __restrict__ att)
{
    int t = blockIdx.x * 256 + threadIdx.x;
    if (t >= NQH * 4) return;
    int qidx = t >> 2, d4 = t & 3;
    float m0 = pm[qidx*2], m1 = pm[qidx*2+1];
    float l0 = pl[qidx*2], l1 = pl[qidx*2+1];
    float m = fmaxf(m0, m1);
    float e0 = __expf(m0 - m), e1 = __expf(m1 - m);
    float inv = 1.f / (l0 * e0 + l1 * e1);
    float4 a = reinterpret_cast<const float4*>(po + (size_t)qidx*32)[d4];
    float4 c = reinterpret_cast<const float4*>(po + (size_t)qidx*32 + 16)[d4];
    float4 o;
    o.x = (a.x*e0 + c.x*e1) * inv;
    o.y = (a.y*e0 + c.y*e1) * inv;
    o.z = (a.z*e0 + c.z*e1) * inv;
    o.w = (a.w*e0 + c.w*e1) * inv;
    int bh = qidx / LQ, qi = qidx - bh * LQ;
    int b = bh >> 2, h = bh & 3;
    reinterpret_cast<float4*>(att + ((size_t)(b*LQ + qi))*64 + h*16)[d4] = o;
}

// ---------------- AWG top-16, split-K: phase 1 (per-half top-16 list) -------
__global__ __launch_bounds__(256, 3)
void attn_topk_p1(const float* __restrict__ qp, const float* __restrict__ kp,
                  float* __restrict__ tp)
{
    extern __shared__ float4 sK[];   // 375*4 float4 = 24 KB
    const int bh = blockIdx.y >> 1, half = blockIdx.y & 1;
    const int b = bh >> 2, h = bh & 3;
    const int j0 = half * LKH;
    const float* kb = kp + ((size_t)(b * LKk + j0)) * Cc + h * 16;
    for (int idx = threadIdx.x; idx < LKH * 4; idx += 256) {
        int j = idx >> 2, d = idx & 3;
        sK[idx] = *reinterpret_cast<const float4*>(kb + (size_t)j * Cc + d * 4);
    }
    __syncthreads();

    int qi = blockIdx.x * 256 + threadIdx.x;
    if (qi >= LQ) return;
    const float* qr = qp + ((size_t)(b * LQ + qi)) * Cc + h * 16;
    float4 q0 = *reinterpret_cast<const float4*>(qr + 0);
    float4 q1 = *reinterpret_cast<const float4*>(qr + 4);
    float4 q2 = *reinterpret_cast<const float4*>(qr + 8);
    float4 q3 = *reinterpret_cast<const float4*>(qr + 12);
    const float sc = 0.25f;
    q0.x*=sc;q0.y*=sc;q0.z*=sc;q0.w*=sc; q1.x*=sc;q1.y*=sc;q1.z*=sc;q1.w*=sc;
    q2.x*=sc;q2.y*=sc;q2.z*=sc;q2.w*=sc; q3.x*=sc;q3.y*=sc;q3.z*=sc;q3.w*=sc;

    float t[16];
#pragma unroll
    for (int k = 0; k < 16; k++) t[k] = -3.4e38f;
    for (int j = 0; j < LKH; j++) {
        const float4* kj = &sK[j * 4];
        float4 k0 = kj[0], k1 = kj[1], k2 = kj[2], k3 = kj[3];
        float s = q0.x*k0.x + q0.y*k0.y + q0.z*k0.z + q0.w*k0.w
                + q1.x*k1.x + q1.y*k1.y + q1.z*k1.z + q1.w*k1.w
                + q2.x*k2.x + q2.y*k2.y + q2.z*k2.z + q2.w*k2.w
                + q3.x*k3.x + q3.y*k3.y + q3.z*k3.z + q3.w*k3.w;
#pragma unroll
        for (int u = 0; u < 15; u++)
            t[u] = fminf(t[u+1], fmaxf(t[u], s));
        t[15] = fmaxf(t[15], s);
    }
    size_t idx = (size_t)bh * LQ + qi;
    float* tq = tp + (idx*2 + half) * 16;
#pragma unroll
    for (int k = 0; k < 16; k++) tq[k] = t[k];
}

// merge two sorted-16 lists: thr = 16th largest of union, m = max
__global__ __launch_bounds__(256)
void attn_topk_thr(const float* __restrict__ tp, float* __restrict__ thrm)
{
    int qidx = blockIdx.x * 256 + threadIdx.x;
    if (qidx >= NQH) return;
    const float4* a = reinterpret_cast<const float4*>(tp + (size_t)qidx*32);
    float4 a0 = a[0], a1 = a[1], a2 = a[2], a3 = a[3];
    float4 c0 = a[4], c1 = a[5], c2 = a[6], c3 = a[7];
    // top-16 of union = pairwise max(asc[i], asc'[15-i]); thr = min of those
    float thr = fmaxf(a0.x, c3.w);
    thr = fminf(thr, fmaxf(a0.y, c3.z));
    thr = fminf(thr, fmaxf(a0.z, c3.y));
    thr = fminf(thr, fmaxf(a0.w, c3.x));
    thr = fminf(thr, fmaxf(a1.x, c2.w));
    thr = fminf(thr, fmaxf(a1.y, c2.z));
    thr = fminf(thr, fmaxf(a1.z, c2.y));
    thr = fminf(thr, fmaxf(a1.w, c2.x));
    thr = fminf(thr, fmaxf(a2.x, c1.w));
    thr = fminf(thr, fmaxf(a2.y, c1.z));
    thr = fminf(thr, fmaxf(a2.z, c1.y));
    thr = fminf(thr, fmaxf(a2.w, c1.x));
    thr = fminf(thr, fmaxf(a3.x, c0.w));
    thr = fminf(thr, fmaxf(a3.y, c0.z));
    thr = fminf(thr, fmaxf(a3.z, c0.y));
    thr = fminf(thr, fmaxf(a3.w, c0.x));
    thrm[qidx*2]     = thr;
    thrm[qidx*2 + 1] = fmaxf(a3.w, c3.w);
}

// phase 2: per-half gated accumulation with global (thr, m)
__global__ __launch_bounds__(256, 3)
void attn_topk_p2(const float* __restrict__ qp, const float* __restrict__ kp,
                  const float* __restrict__ vp, const float* __restrict__ thrm,
                  float* __restrict__ pl, float* __restrict__ po)
{
    extern __shared__ float4 sK[];   // 24 KB
    const int bh = blockIdx.y >> 1, half = blockIdx.y & 1;
    const int b = bh >> 2, h = bh & 3;
    const int j0 = half * LKH;
    const float* kb = kp + ((size_t)(b * LKk + j0)) * Cc + h * 16;
    const float* vb = vp + ((size_t)(b * LKk + j0)) * Cc + h * 16;
    for (int idx = threadIdx.x; idx < LKH * 4; idx += 256) {
        int j = idx >> 2, d = idx & 3;
        sK[idx] = *reinterpret_cast<const float4*>(kb + (size_t)j * Cc + d * 4);
    }
    __syncthreads();

    int qi = blockIdx.x * 256 + threadIdx.x;
    if (qi >= LQ) return;
    const float* qr = qp + ((size_t)(b * LQ + qi)) * Cc + h * 16;
    float4 q0 = *reinterpret_cast<const float4*>(qr + 0);
    float4 q1 = *reinterpret_cast<const float4*>(qr + 4);
    float4 q2 = *reinterpret_cast<const float4*>(qr + 8);
    float4 q3 = *reinterpret_cast<const float4*>(qr + 12);
    const float sc = 0.25f;
    q0.x*=sc;q0.y*=sc;q0.z*=sc;q0.w*=sc; q1.x*=sc;q1.y*=sc;q1.z*=sc;q1.w*=sc;
    q2.x*=sc;q2.y*=sc;q2.z*=sc;q2.w*=sc; q3.x*=sc;q3.y*=sc;q3.z*=sc;q3.w*=sc;

    size_t idx = (size_t)bh * LQ + qi;
    const float thr = thrm[idx*2];
    const float m   = thrm[idx*2 + 1];

    float l = 0.f;
    float4 o0 = {0,0,0,0}, o1v = {0,0,0,0}, o2 = {0,0,0,0}, o3 = {0,0,0,0};
    for (int j = 0; j < LKH; j++) {
        const float4* kj = &sK[j * 4];
        float4 k0 = kj[0], k1 = kj[1], k2 = kj[2], k3 = kj[3];
        float s = q0.x*k0.x + q0.y*k0.y + q0.z*k0.z + q0.w*k0.w
                + q1.x*k1.x + q1.y*k1.y + q1.z*k1.z + q1.w*k1.w
                + q2.x*k2.x + q2.y*k2.y + q2.z*k2.z + q2.w*k2.w
                + q3.x*k3.x + q3.y*k3.y + q3.z*k3.z + q3.w*k3.w;
        if (s >= thr) {
            float p = __expf(s - m);
            l += p;
            const float4* vr = reinterpret_cast<const float4*>(vb + (size_t)j * Cc);
            float4 v0 = __ldg(&vr[0]), v1 = __ldg(&vr[1]);
            float4 v2 = __ldg(&vr[2]), v3 = __ldg(&vr[3]);
            o0.x += p*v0.x; o0.y += p*v0.y; o0.z += p*v0.z; o0.w += p*v0.w;
            o1v.x += p*v1.x; o1v.y += p*v1.y; o1v.z += p*v1.z; o1v.w += p*v1.w;
            o2.x += p*v2.x; o2.y += p*v2.y; o2.z += p*v2.z; o2.w += p*v2.w;
            o3.x += p*v3.x; o3.y += p*v3.y; o3.z += p*v3.z; o3.w += p*v3.w;
        }
    }
    pl[idx*2 + half] = l;
    float4* pov = reinterpret_cast<float4*>(po + (idx*2 + half) * 16);
    pov[0] = o0; pov[1] = o1v; pov[2] = o2; pov[3] = o3;
}

// combine topk partials (shared m -> straight sum) -> att
__global__ __launch_bounds__(256)
void attn_topk_combine(const float* __restrict__ pl, const float* __restrict__ po,
                       float* __restrict__ att)
{
    int t = blockIdx.x * 256 + threadIdx.x;
    if (t >= NQH * 4) return;
    int qidx = t >> 2, d4 = t & 3;
    float inv = 1.f / (pl[qidx*2] + pl[qidx*2+1]);
    float4 a = reinterpret_cast<const float4*>(po + (size_t)qidx*32)[d4];
    float4 c = reinterpret_cast<const float4*>(po + (size_t)qidx*32 + 16)[d4];
    float4 o;
    o.x = (a.x + c.x) * inv; o.y = (a.y + c.y) * inv;
    o.z = (a.z + c.z) * inv; o.w = (a.w + c.w) * inv;
    int bh = qidx / LQ, qi = qidx - bh * LQ;
    int b = bh >> 2, h = bh & 3;
    reinterpret_cast<float4*>(att + ((size_t)(b*LQ + qi))*64 + h*16)[d4] = o;
}

// ---------------- host orchestration ----------------------------------------
extern "C" void kernel_launch(void* const* d_in, const int* in_sizes, int n_in,
                              void* d_out, int out_size)
{
    const float* q        = (const float*)d_in[0];
    const float* enc      = (const float*)d_in[1];
    const float* cal_Wq   = (const float*)d_in[2];
    const float* cal_Wk   = (const float*)d_in[3];
    const float* cal_Wv   = (const float*)d_in[4];
    const float* cal_Wo   = (const float*)d_in[5];
    const float* cal_ln1g = (const float*)d_in[6];
    const float* cal_ln1b = (const float*)d_in[7];
    const float* cal_W1   = (const float*)d_in[8];
    const float* cal_b1   = (const float*)d_in[9];
    const float* cal_W2   = (const float*)d_in[10];
    const float* cal_b2   = (const float*)d_in[11];
    const float* cal_ln2g = (const float*)d_in[12];
    const float* cal_ln2b = (const float*)d_in[13];
    const float* m_ln_g   = (const float*)d_in[14];
    const float* m_ln_b   = (const float*)d_in[15];
    const float* m_fc1_W  = (const float*)d_in[16];
    const float* m_fc1_b  = (const float*)d_in[17];
    const float* m_fc2_W  = (const float*)d_in[18];
    const float* m_fc2_b  = (const float*)d_in[19];
    const float* m_Wq     = (const float*)d_in[20];
    const float* m_Wk     = (const float*)d_in[21];
    const float* m_Wv     = (const float*)d_in[22];
    const float* m_Wo     = (const float*)d_in[23];
    const float* m_aln_g  = (const float*)d_in[24];
    const float* m_aln_b  = (const float*)d_in[25];
    const float* fc_W     = (const float*)d_in[26];
    const float* fc_b     = (const float*)d_in[27];

    float *qp, *kp, *vp, *att, *x, *h1, *x2, *qnA, *qnB, *sg, *xn;
    float *pm, *pl, *po, *tp, *thrm;
    cudaGetSymbolAddress((void**)&qp,  g_qp);
    cudaGetSymbolAddress((void**)&kp,  g_kp);
    cudaGetSymbolAddress((void**)&vp,  g_vp);
    cudaGetSymbolAddress((void**)&att, g_att);
    cudaGetSymbolAddress((void**)&x,   g_x);
    cudaGetSymbolAddress((void**)&h1,  g_h1);
    cudaGetSymbolAddress((void**)&x2,  g_x2);
    cudaGetSymbolAddress((void**)&qnA, g_qnA);
    cudaGetSymbolAddress((void**)&qnB, g_qnB);
    cudaGetSymbolAddress((void**)&sg,  g_sg);
    cudaGetSymbolAddress((void**)&xn,  g_xn);
    cudaGetSymbolAddress((void**)&pm,  g_pm);
    cudaGetSymbolAddress((void**)&pl,  g_pl);
    cudaGetSymbolAddress((void**)&po,  g_po);
    cudaGetSymbolAddress((void**)&tp,  g_tp);
    cudaGetSymbolAddress((void**)&thrm,g_thrm);

    cudaFuncSetAttribute((proj_kernel<64,256,4,1>), cudaFuncAttributeMaxDynamicSharedMemorySize, 65536);
    cudaFuncSetAttribute((gemm_ln_kernel<256>),     cudaFuncAttributeMaxDynamicSharedMemorySize, 65536);

    const int smem64   = 64 * 64 * 4;           // 16 KB
    const int smemFFN  = 65536;                 // 64 KB
    const int smemAP   = LKH * 64 * 2;          // 48000 B (K+V half)
    const int smemAK   = LKH * 64;              // 24000 B (K half)
    dim3 agrid((LQ + 255) / 256, Bq * NHh * 2); // (12, 32)
    const int gP = RQ / 32;                     // 375 (exact)
    const int gKV = (RK + 15) / 16;             // 188
    const int gC = (NQH * 4 + 255) / 256;       // 750
    const int gT = (NQH + 255) / 256;           // 188

    // ---- cross_attn_layer ----
    proj_kernel<64,64,2,0><<<gP, 256, smem64>>>(q, cal_Wq, nullptr, qp, RQ);
    dual_kernel<0,1><<<gKV, 256>>>(enc, cal_Wk, cal_Wv, nullptr, nullptr, kp, vp, RK);
    attn_plain_part<<<agrid, 256, smemAP>>>(qp, kp, vp, pm, pl, po);
    attn_plain_combine<<<gC, 256>>>(pm, pl, po, att);
    gemm_ln_kernel<64><<<gP, 256, smem64>>>(att, cal_Wo, q, nullptr,
        cal_ln1g, cal_ln1b, nullptr, nullptr, nullptr, nullptr, nullptr, nullptr,
        x, nullptr, nullptr, RQ);
    proj_kernel<64,256,4,1><<<RQ/16, 256, smemFFN>>>(x, cal_W1, cal_b1, h1, RQ);
    // FFN2 + LN2 -> x2, fused LN(m_ln[0]) -> qnA
    gemm_ln_kernel<256><<<gP, 256, smemFFN>>>(h1, cal_W2, x, cal_b2,
        cal_ln2g, cal_ln2b, nullptr, nullptr, m_ln_g, m_ln_b, nullptr, nullptr,
        x2, qnA, nullptr, RQ);

    // ---- MGAN decoder layers ----
    float* qncur = qnA;
    float* qnnxt = qnB;
    for (int i = 0; i < 2; i++) {
        dual_kernel<1,2><<<gP, 256>>>(qncur, m_fc1_W + i*4096, m_fc2_W + i*4096,
                                      m_fc1_b + i*64, m_fc2_b + i*64, sg, nullptr, RQ);
        proj_kernel<64,64,2,0><<<gP, 256, smem64>>>(sg, m_Wq + i*4096, nullptr, qp, RQ);
        dual_kernel<0,1><<<gKV, 256>>>(enc, m_Wk + i*4096, m_Wv + i*4096,
                                       nullptr, nullptr, kp, vp, RK);
        attn_topk_p1<<<agrid, 256, smemAK>>>(qp, kp, tp);
        attn_topk_thr<<<gT, 256>>>(tp, thrm);
        attn_topk_p2<<<agrid, 256, smemAK>>>(qp, kp, vp, thrm, pl, po);
        attn_topk_combine<<<gC, 256>>>(pl, po, att);
        // Wo GEMM + aln LN + GLU; fuse next-layer LN (i==0) or head (i==1)
        if (i == 0) {
            gemm_ln_kernel<64><<<gP, 256, smem64>>>(att, m_Wo + i*4096, sg, nullptr,
                m_aln_g + i*64, m_aln_b + i*64, qncur, sg,
                m_ln_g + 64, m_ln_b + 64, nullptr, nullptr,
                x2, qnnxt, nullptr, RQ);
        } else {
            gemm_ln_kernel<64><<<gP, 256, smem64>>>(att, m_Wo + i*4096, sg, nullptr,
                m_aln_g + i*64, m_aln_b + i*64, qncur, sg,
                nullptr, nullptr, fc_W, fc_b,
                xn, nullptr, (float*)d_out, RQ);
        }
        float* tmp = qncur; qncur = qnnxt; qnnxt = tmp;
    }
}